// round 3
// baseline (speedup 1.0000x reference)
#include <cuda_runtime.h>
#include <cuda_bf16.h>
#include <cstdint>
#include <cstddef>

// Problem constants
#define BB    32
#define DD    512
#define NN    4096
#define KK    64
#define DTILE 128          // d rows per CTA
#define NC    64           // n elements per stage (64 bf16 = 128B row)
#define NITER (NN / NC)    // 64

// SMEM stage layout: x tile 128 rows x 128B = 16KB, a tile 64 x 128B = 8KB
#define STG_BYTES  24576
#define STG_AOFF   16384
#define OFF_ASUM   (2 * STG_BYTES)          // 64 floats
#define SMEM_TOTAL (OFF_ASUM + 256 + 1024)  // + alignment slack

__device__ __forceinline__ uint32_t smem_u32(const void* p) {
    uint32_t a;
    asm("{ .reg .u64 t; cvta.to.shared.u64 t, %1; cvt.u32.u64 %0, t; }" : "=r"(a) : "l"(p));
    return a;
}

__device__ __forceinline__ void sts8(uint32_t addr, uint32_t a, uint32_t b) {
    asm volatile("st.shared.v2.b32 [%0], {%1, %2};" :: "r"(addr), "r"(a), "r"(b) : "memory");
}

__device__ __forceinline__ void ldsm4(uint32_t* r, uint32_t addr) {
    asm volatile("ldmatrix.sync.aligned.m8n8.x4.shared.b16 {%0,%1,%2,%3}, [%4];"
                 : "=r"(r[0]), "=r"(r[1]), "=r"(r[2]), "=r"(r[3]) : "r"(addr));
}

__device__ __forceinline__ void mma16816(float* d, const uint32_t* a, uint32_t b0, uint32_t b1) {
    asm volatile(
        "mma.sync.aligned.m16n8k16.row.col.f32.bf16.bf16.f32 "
        "{%0,%1,%2,%3}, {%4,%5,%6,%7}, {%8,%9}, {%0,%1,%2,%3};"
        : "+f"(d[0]), "+f"(d[1]), "+f"(d[2]), "+f"(d[3])
        : "r"(a[0]), "r"(a[1]), "r"(a[2]), "r"(a[3]), "r"(b0), "r"(b1));
}

__device__ __forceinline__ void cvt4(const float4& v, uint32_t& lo, uint32_t& hi) {
    __nv_bfloat162 l = __floats2bfloat162_rn(v.x, v.y);
    __nv_bfloat162 h = __floats2bfloat162_rn(v.z, v.w);
    lo = *reinterpret_cast<uint32_t*>(&l);
    hi = *reinterpret_cast<uint32_t*>(&h);
}

// scratch for a_sum (no cudaMalloc allowed)
__device__ float g_asum[BB * KK];

// ---------------------------------------------------------------------------
// Pre-kernel: a_sum[b,k] = sum_n a_bar[b,k,n].  One warp per (b,k) row.
// ---------------------------------------------------------------------------
__global__ void asum_kernel(const float* __restrict__ a) {
    int w = (blockIdx.x * blockDim.x + threadIdx.x) >> 5;
    int lane = threadIdx.x & 31;
    if (w >= BB * KK) return;
    const float4* p = (const float4*)(a + (size_t)w * NN);
    float s = 0.f;
#pragma unroll 8
    for (int i = 0; i < 32; i++) {
        float4 v = p[lane + 32 * i];
        s += (v.x + v.y) + (v.z + v.w);
    }
#pragma unroll
    for (int o = 16; o; o >>= 1) s += __shfl_xor_sync(0xFFFFFFFFu, s, o);
    if (lane == 0) g_asum[w] = s;
}

// ---------------------------------------------------------------------------
// Main: per CTA (b, dt): D[128 d, 64 k] = X(128 x n) @ Abar^T via mma.sync
// bf16, double-buffered 64-n stages, fp32 epilogue - a_sum[k]*c[k,d].
// 256 threads / 8 warps; warp tile 32(d) x 32(k).
// ---------------------------------------------------------------------------
__global__ void __launch_bounds__(256, 1)
vlad_main(const float* __restrict__ x, const float* __restrict__ ab,
          const float* __restrict__ cmat, float* __restrict__ out) {
    extern __shared__ __align__(16) char smem_raw[];
    const uint32_t sb0 = (smem_u32(smem_raw) + 1023) & ~1023u;
    float* asum_s = reinterpret_cast<float*>(smem_raw + ((sb0 - smem_u32(smem_raw)) + OFF_ASUM));

    const int tid  = threadIdx.x;
    const int warp = tid >> 5, lane = tid & 31;
    const int b  = blockIdx.x >> 2;
    const int dt = blockIdx.x & 3;

    if (tid < KK) asum_s[tid] = g_asum[b * KK + tid];

    // Per-thread gmem mapping: x 8 float4/stage, a 4 float4/stage
    const float* xbase = x  + ((size_t)b * DD + (size_t)dt * DTILE) * NN;
    const float* abase = ab + (size_t)b * KK * NN;

    // STS swizzled offsets (within a stage buffer)
    uint32_t xsts[8], asts[4];
#pragma unroll
    for (int j = 0; j < 8; j++) {
        int ci = tid + 256 * j, row = ci >> 4, c4 = ci & 15;
        uint32_t off = (uint32_t)((row << 7) + (c4 << 3));
        xsts[j] = off ^ ((off >> 3) & 0x70);
    }
#pragma unroll
    for (int j = 0; j < 4; j++) {
        int ci = tid + 256 * j, row = ci >> 4, c4 = ci & 15;
        uint32_t off = (uint32_t)((row << 7) + (c4 << 3));
        asts[j] = off ^ ((off >> 3) & 0x70);
    }

    // ldmatrix source offsets (within stage buffer), per warp/lane
    const int wm = (warp >> 1) * 32, wn = (warp & 1) * 32;
    const int g = lane >> 3, r = lane & 7;
    uint32_t offA[2], offB[2];
#pragma unroll
    for (int i = 0; i < 2; i++) {
        int row = wm + i * 16 + (g & 1) * 8 + r;
        uint32_t gk = (uint32_t)((g >> 1) * 16);
        offA[i] = (uint32_t)(row << 7) + (gk ^ (uint32_t)((row & 7) << 4));
    }
#pragma unroll
    for (int nb = 0; nb < 2; nb++) {
        int row = wn + nb * 16 + (g >> 1) * 8 + r;
        uint32_t gk = (uint32_t)((g & 1) * 16);
        offB[nb] = (uint32_t)(row << 7) + (gk ^ (uint32_t)((row & 7) << 4)) + STG_AOFF;
    }

    float acc[2][4][4];
#pragma unroll
    for (int i = 0; i < 2; i++)
#pragma unroll
        for (int j = 0; j < 4; j++)
#pragma unroll
            for (int e = 0; e < 4; e++) acc[i][j][e] = 0.f;

    float4 xr[8], ar[4];

    // ---- prologue: load + store stage 0 ----
#pragma unroll
    for (int j = 0; j < 8; j++) {
        int ci = tid + 256 * j, row = ci >> 4, c4 = ci & 15;
        xr[j] = *reinterpret_cast<const float4*>(xbase + (size_t)row * NN + (c4 << 2));
    }
#pragma unroll
    for (int j = 0; j < 4; j++) {
        int ci = tid + 256 * j, row = ci >> 4, c4 = ci & 15;
        ar[j] = *reinterpret_cast<const float4*>(abase + (size_t)row * NN + (c4 << 2));
    }
#pragma unroll
    for (int j = 0; j < 8; j++) { uint32_t lo, hi; cvt4(xr[j], lo, hi); sts8(sb0 + xsts[j], lo, hi); }
#pragma unroll
    for (int j = 0; j < 4; j++) { uint32_t lo, hi; cvt4(ar[j], lo, hi); sts8(sb0 + STG_AOFF + asts[j], lo, hi); }

    for (int it = 0; it < NITER; ++it) {
        __syncthreads();                       // stage (it&1) visible to all

        // prefetch next stage into registers (hidden under compute)
        if (it + 1 < NITER) {
            const int nb2 = (it + 1) * NC;
#pragma unroll
            for (int j = 0; j < 8; j++) {
                int ci = tid + 256 * j, row = ci >> 4, c4 = ci & 15;
                xr[j] = *reinterpret_cast<const float4*>(xbase + (size_t)row * NN + nb2 + (c4 << 2));
            }
#pragma unroll
            for (int j = 0; j < 4; j++) {
                int ci = tid + 256 * j, row = ci >> 4, c4 = ci & 15;
                ar[j] = *reinterpret_cast<const float4*>(abase + (size_t)row * NN + nb2 + (c4 << 2));
            }
        }

        // compute current stage
        const uint32_t bs = sb0 + (uint32_t)(it & 1) * STG_BYTES;
#pragma unroll
        for (int ks = 0; ks < 4; ks++) {
            uint32_t aF0[4], aF1[4], bF0[4], bF1[4];
            const uint32_t kx = (uint32_t)(ks << 5);
            ldsm4(aF0, (bs + offA[0]) ^ kx);
            ldsm4(aF1, (bs + offA[1]) ^ kx);
            ldsm4(bF0, (bs + offB[0]) ^ kx);
            ldsm4(bF1, (bs + offB[1]) ^ kx);
            mma16816(acc[0][0], aF0, bF0[0], bF0[1]);
            mma16816(acc[0][1], aF0, bF0[2], bF0[3]);
            mma16816(acc[0][2], aF0, bF1[0], bF1[1]);
            mma16816(acc[0][3], aF0, bF1[2], bF1[3]);
            mma16816(acc[1][0], aF1, bF0[0], bF0[1]);
            mma16816(acc[1][1], aF1, bF0[2], bF0[3]);
            mma16816(acc[1][2], aF1, bF1[0], bF1[1]);
            mma16816(acc[1][3], aF1, bF1[2], bF1[3]);
        }

        // store next stage into other buffer
        if (it + 1 < NITER) {
            const uint32_t ns = sb0 + (uint32_t)((it + 1) & 1) * STG_BYTES;
#pragma unroll
            for (int j = 0; j < 8; j++) { uint32_t lo, hi; cvt4(xr[j], lo, hi); sts8(ns + xsts[j], lo, hi); }
#pragma unroll
            for (int j = 0; j < 4; j++) { uint32_t lo, hi; cvt4(ar[j], lo, hi); sts8(ns + STG_AOFF + asts[j], lo, hi); }
        }
    }

    // ---- epilogue: V = wx - a_sum[k]*c[k,d], out[d,k,b] ----
    const int mrow = lane >> 2, ncol = (lane & 3) * 2;
#pragma unroll
    for (int i = 0; i < 2; i++) {
#pragma unroll
        for (int j = 0; j < 4; j++) {
            const int k0 = wn + j * 8 + ncol;
            const int d0 = dt * DTILE + wm + i * 16 + mrow;
            const float as0 = asum_s[k0], as1 = asum_s[k0 + 1];
#pragma unroll
            for (int rr = 0; rr < 2; rr++) {          // rows d0, d0+8
                const int d = d0 + rr * 8;
                float v0 = acc[i][j][rr * 2 + 0] - as0 * __ldg(cmat + (size_t)k0 * DD + d);
                float v1 = acc[i][j][rr * 2 + 1] - as1 * __ldg(cmat + (size_t)(k0 + 1) * DD + d);
                out[(size_t)d * KK * BB + (size_t)k0 * BB + b] = v0;
                out[(size_t)d * KK * BB + (size_t)(k0 + 1) * BB + b] = v1;
            }
        }
    }
}

extern "C" void kernel_launch(void* const* d_in, const int* in_sizes, int n_in,
                              void* d_out, int out_size) {
    (void)in_sizes; (void)n_in; (void)out_size;
    const float* x  = (const float*)d_in[0];
    const float* ab = (const float*)d_in[1];
    const float* c  = (const float*)d_in[2];
    float* out = (float*)d_out;

    asum_kernel<<<256, 256>>>(ab);

    cudaFuncSetAttribute(vlad_main, cudaFuncAttributeMaxDynamicSharedMemorySize, SMEM_TOTAL);
    vlad_main<<<BB * 4, 256, SMEM_TOTAL>>>(x, ab, c, out);
}

// round 5
// speedup vs baseline: 1.1014x; 1.1014x over previous
#include <cuda_runtime.h>
#include <cuda_bf16.h>
#include <cstdint>
#include <cstddef>

// Problem constants
#define BB    32
#define DD    512
#define NN    4096
#define KK    64
#define DTILE 64           // d rows per CTA
#define NC    64           // n elements per stage (64 bf16 = 128B row)
#define NITER (NN / NC)    // 64

// SMEM stage layout: x tile 64 rows x 128B = 8KB, a tile 64 x 128B = 8KB
#define STG_BYTES  16384
#define STG_AOFF   8192
#define OFF_ASUM   (2 * STG_BYTES)          // 64 floats
#define SMEM_TOTAL (OFF_ASUM + 256 + 1024)  // + alignment slack

__device__ __forceinline__ uint32_t smem_u32(const void* p) {
    uint32_t a;
    asm("{ .reg .u64 t; cvta.to.shared.u64 t, %1; cvt.u32.u64 %0, t; }" : "=r"(a) : "l"(p));
    return a;
}

__device__ __forceinline__ void sts8(uint32_t addr, uint32_t a, uint32_t b) {
    asm volatile("st.shared.v2.b32 [%0], {%1, %2};" :: "r"(addr), "r"(a), "r"(b) : "memory");
}

__device__ __forceinline__ void ldsm4(uint32_t* r, uint32_t addr) {
    asm volatile("ldmatrix.sync.aligned.m8n8.x4.shared.b16 {%0,%1,%2,%3}, [%4];"
                 : "=r"(r[0]), "=r"(r[1]), "=r"(r[2]), "=r"(r[3]) : "r"(addr));
}

__device__ __forceinline__ void mma16816(float* d, const uint32_t* a, uint32_t b0, uint32_t b1) {
    asm volatile(
        "mma.sync.aligned.m16n8k16.row.col.f32.bf16.bf16.f32 "
        "{%0,%1,%2,%3}, {%4,%5,%6,%7}, {%8,%9}, {%0,%1,%2,%3};"
        : "+f"(d[0]), "+f"(d[1]), "+f"(d[2]), "+f"(d[3])
        : "r"(a[0]), "r"(a[1]), "r"(a[2]), "r"(a[3]), "r"(b0), "r"(b1));
}

__device__ __forceinline__ void cvt4(const float4& v, uint32_t& lo, uint32_t& hi) {
    __nv_bfloat162 l = __floats2bfloat162_rn(v.x, v.y);
    __nv_bfloat162 h = __floats2bfloat162_rn(v.z, v.w);
    lo = *reinterpret_cast<uint32_t*>(&l);
    hi = *reinterpret_cast<uint32_t*>(&h);
}

// ---------------------------------------------------------------------------
// Single fused kernel. Per CTA (b, dt): D[64 d, 64 k] = X(64 x n) @ Abar^T
// via mma.sync bf16, double-buffered 64-n stages. a_sum computed in-flight
// from the same a_bar stream. fp32 epilogue: V = wx - a_sum[k]*c[k,d],
// stored to out[d,k,b]. 256 threads / 8 warps; warp tile 16(d) x 32(k).
// 2 CTAs/SM so one CTA's sync bubbles are filled by the other's loads.
// ---------------------------------------------------------------------------
__global__ void __launch_bounds__(256, 2)
vlad_main(const float* __restrict__ x, const float* __restrict__ ab,
          const float* __restrict__ cmat, float* __restrict__ out) {
    extern __shared__ __align__(16) char smem_raw[];
    const uint32_t sbr = smem_u32(smem_raw);
    const uint32_t sb0 = (sbr + 1023) & ~1023u;
    float* asum_s = reinterpret_cast<float*>(smem_raw + (sb0 - sbr) + OFF_ASUM);

    const int tid  = threadIdx.x;
    const int warp = tid >> 5, lane = tid & 31;
    const int b  = blockIdx.x >> 3;
    const int dt = blockIdx.x & 7;

    const float* xbase = x  + ((size_t)b * DD + (size_t)dt * DTILE) * NN;
    const float* abase = ab + (size_t)b * KK * NN;

    // STS swizzled offsets (within a stage buffer): 1024 float4 per tile,
    // 4 per thread; ci = tid + 256j -> row = ci>>4, c4 = ci&15.
    uint32_t sts_off[4];
#pragma unroll
    for (int j = 0; j < 4; j++) {
        int ci = tid + 256 * j, row = ci >> 4, c4 = ci & 15;
        uint32_t off = (uint32_t)((row << 7) + (c4 << 3));
        sts_off[j] = off ^ ((off >> 3) & 0x70);
    }

    // ldmatrix source offsets, per warp/lane. Warp tile: 16(m) x 32(n).
    const int wm = (warp & 3) * 16, wn = (warp >> 2) * 32;
    const int g = lane >> 3, r = lane & 7;
    uint32_t offA, offB[2];
    {
        int row = wm + (g & 1) * 8 + r;
        uint32_t gk = (uint32_t)((g >> 1) * 16);
        offA = (uint32_t)(row << 7) + (gk ^ (uint32_t)((row & 7) << 4));
    }
#pragma unroll
    for (int nb = 0; nb < 2; nb++) {
        int row = wn + nb * 16 + (g >> 1) * 8 + r;
        uint32_t gk = (uint32_t)((g & 1) * 16);
        offB[nb] = (uint32_t)(row << 7) + (gk ^ (uint32_t)((row & 7) << 4)) + STG_AOFF;
    }

    float acc[4][4];
#pragma unroll
    for (int j = 0; j < 4; j++)
#pragma unroll
        for (int e = 0; e < 4; e++) acc[j][e] = 0.f;
    float asum_p[4] = {0.f, 0.f, 0.f, 0.f};

    float4 xr[4], ar[4];

    // ---- prologue: load + store stage 0 ----
#pragma unroll
    for (int j = 0; j < 4; j++) {
        int ci = tid + 256 * j, row = ci >> 4, c4 = ci & 15;
        xr[j] = *reinterpret_cast<const float4*>(xbase + (size_t)row * NN + (c4 << 2));
        ar[j] = *reinterpret_cast<const float4*>(abase + (size_t)row * NN + (c4 << 2));
    }
#pragma unroll
    for (int j = 0; j < 4; j++) {
        uint32_t lo, hi;
        cvt4(xr[j], lo, hi); sts8(sb0 + sts_off[j], lo, hi);
        cvt4(ar[j], lo, hi); sts8(sb0 + STG_AOFF + sts_off[j], lo, hi);
        asum_p[j] += (ar[j].x + ar[j].y) + (ar[j].z + ar[j].w);
    }

    for (int it = 0; it < NITER; ++it) {
        __syncthreads();                       // stage (it&1) visible to all

        // prefetch next stage into registers (hidden under compute)
        if (it + 1 < NITER) {
            const int nb2 = (it + 1) * NC;
#pragma unroll
            for (int j = 0; j < 4; j++) {
                int ci = tid + 256 * j, row = ci >> 4, c4 = ci & 15;
                xr[j] = *reinterpret_cast<const float4*>(xbase + (size_t)row * NN + nb2 + (c4 << 2));
                ar[j] = *reinterpret_cast<const float4*>(abase + (size_t)row * NN + nb2 + (c4 << 2));
            }
        }

        // compute current stage
        const uint32_t bs = sb0 + (uint32_t)(it & 1) * STG_BYTES;
#pragma unroll
        for (int ks = 0; ks < 4; ks++) {
            uint32_t aF[4], bF0[4], bF1[4];
            const uint32_t kx = (uint32_t)(ks << 5);
            ldsm4(aF,  (bs + offA) ^ kx);
            ldsm4(bF0, (bs + offB[0]) ^ kx);
            ldsm4(bF1, (bs + offB[1]) ^ kx);
            mma16816(acc[0], aF, bF0[0], bF0[1]);
            mma16816(acc[1], aF, bF0[2], bF0[3]);
            mma16816(acc[2], aF, bF1[0], bF1[1]);
            mma16816(acc[3], aF, bF1[2], bF1[3]);
        }

        // store next stage into other buffer; fold a into running a_sum
        if (it + 1 < NITER) {
            const uint32_t ns = sb0 + (uint32_t)((it + 1) & 1) * STG_BYTES;
#pragma unroll
            for (int j = 0; j < 4; j++) {
                uint32_t lo, hi;
                cvt4(xr[j], lo, hi); sts8(ns + sts_off[j], lo, hi);
                cvt4(ar[j], lo, hi); sts8(ns + STG_AOFF + sts_off[j], lo, hi);
                asum_p[j] += (ar[j].x + ar[j].y) + (ar[j].z + ar[j].w);
            }
        }
    }

    // ---- a_sum reduction: thread's asum_p[j] covers k = (tid>>4)%... ----
    // Row of a tile handled by thread = ci>>4 where ci = tid + 256j, so
    // k = (tid + 256j)>>4. 16 consecutive lanes (same tid>>4 group) share a
    // row -> xor-reduce over offsets 1,2,4,8.
#pragma unroll
    for (int j = 0; j < 4; j++) {
#pragma unroll
        for (int o = 1; o < 16; o <<= 1)
            asum_p[j] += __shfl_xor_sync(0xFFFFFFFFu, asum_p[j], o);
    }
    if ((lane & 15) == 0) {
        int q = tid >> 4;
#pragma unroll
        for (int j = 0; j < 4; j++) asum_s[q + 16 * j] = asum_p[j];
    }
    __syncthreads();

    // ---- epilogue: V = wx - a_sum[k]*c[k,d], out[d,k,b] ----
    const int mrow = lane >> 2, ncol = (lane & 3) * 2;
#pragma unroll
    for (int j = 0; j < 4; j++) {
        const int k0 = wn + j * 8 + ncol;
        const int d0 = dt * DTILE + wm + mrow;
        const float as0 = asum_s[k0], as1 = asum_s[k0 + 1];
#pragma unroll
        for (int rr = 0; rr < 2; rr++) {          // rows d0, d0+8
            const int d = d0 + rr * 8;
            float v0 = acc[j][rr * 2 + 0] - as0 * __ldg(cmat + (size_t)k0 * DD + d);
            float v1 = acc[j][rr * 2 + 1] - as1 * __ldg(cmat + (size_t)(k0 + 1) * DD + d);
            out[(size_t)d * KK * BB + (size_t)k0 * BB + b] = v0;
            out[(size_t)d * KK * BB + (size_t)(k0 + 1) * BB + b] = v1;
        }
    }
}

extern "C" void kernel_launch(void* const* d_in, const int* in_sizes, int n_in,
                              void* d_out, int out_size) {
    (void)in_sizes; (void)n_in; (void)out_size;
    const float* x  = (const float*)d_in[0];
    const float* ab = (const float*)d_in[1];
    const float* c  = (const float*)d_in[2];
    float* out = (float*)d_out;

    cudaFuncSetAttribute(vlad_main, cudaFuncAttributeMaxDynamicSharedMemorySize, SMEM_TOTAL);
    vlad_main<<<BB * 8, 256, SMEM_TOTAL>>>(x, ab, c, out);
}